// round 10
// baseline (speedup 1.0000x reference)
#include <cuda_runtime.h>

// Fixed problem shapes (from reference setup_inputs)
constexpr int B_    = 16;
constexpr int HS    = 640;
constexpr int WS    = 640;
constexpr int C_    = 3;
constexpr int NPIX  = 512 * 512;          // N = H_out*W_out = 262144 (2^18)
constexpr int NBITS = 18;                 // log2(NPIX)
constexpr int PPT   = 4;                  // pixels per loop iteration

constexpr int SMS      = 148;
constexpr int CTAS_PSM = 16;
constexpr int GRID     = SMS * CTAS_PSM;          // 2368: every SM gets exactly 16 CTAs
constexpr int BLOCK    = 128;                     // 64 warps/SM -> 100% occ class
constexpr int NTILES   = (B_ * NPIX) / PPT;       // 1,048,576 tiles
constexpr int STRIDE   = GRID * BLOCK;            // 303,104

// Predicated 16B gather: no BSSY/BSYNC, predicated-off lanes issue nothing.
__device__ __forceinline__ float4 ldg_f4_pred(const char* p, int doit) {
    float4 q = make_float4(0.f, 0.f, 0.f, 0.f);
    asm volatile(
        "{\n\t"
        ".reg .pred p;\n\t"
        "setp.ne.s32 p, %5, 0;\n\t"
        "@p ld.global.nc.v4.f32 {%0,%1,%2,%3}, [%4];\n\t"
        "}"
        : "+f"(q.x), "+f"(q.y), "+f"(q.z), "+f"(q.w)
        : "l"(p), "r"(doit));
    return q;
}

__global__ __launch_bounds__(BLOCK, CTAS_PSM)   // <=32 regs, 16 CTAs/SM
void resample_nn_kernel(const float* __restrict__ idx,
                        const float* __restrict__ src,
                        float* __restrict__ out)
{
    const int t0 = blockIdx.x * BLOCK + threadIdx.x;

    #pragma unroll 1
    for (int t = t0; t < NTILES; t += STRIDE) {
        const int g0 = t * PPT;                   // first pixel (global, b*N + n)
        const int b  = g0 >> NBITS;
        const int n0 = g0 & (NPIX - 1);

        // idx layout: [B, 2, N] -> rows at b*2N + n, cols at b*2N + N + n
        const float* idx_b = idx + (size_t)b * 2 * NPIX;
        const float4 r4 = __ldcs(reinterpret_cast<const float4*>(idx_b + n0));
        const float4 c4 = __ldcs(reinterpret_cast<const float4*>(idx_b + NPIX + n0));

        const float rs[PPT] = {r4.x, r4.y, r4.z, r4.w};
        const float cs[PPT] = {c4.x, c4.y, c4.z, c4.w};

        // byte base of this batch's source tile (16B aligned: 640*640*12 % 16 == 0)
        const char* __restrict__ sb =
            reinterpret_cast<const char*>(src) + (size_t)b * HS * WS * C_ * sizeof(float);

        float v[PPT * C_];
        #pragma unroll
        for (int i = 0; i < PPT; i++) {
            // trunc(x + 0.5) -> C int cast truncates toward zero, same semantics
            const int ir = (int)(rs[i] + 0.5f);
            const int ic = (int)(cs[i] + 0.5f);
            const bool valid = (ir >= 0) & (ic >= 0) & (ir < HS) & (ic < WS);
            const int irc = min(max(ir, 0), HS - 1);
            const int icc = min(max(ic, 0), WS - 1);

            const int pix  = irc * WS + icc;      // < 409600
            const int s    = pix * 12;            // byte offset of the 3 floats
            const int base = s & ~15;             // 16B-aligned slot
            const int k    = (s >> 2) & 3;        // word offset within slot (0..3)

            const float4 q0 = __ldg(reinterpret_cast<const float4*>(sb + base));
            // spill into next 16B slot only when k>=2; max read end == tile end (no OOB)
            const float4 q1 = ldg_f4_pred(sb + base + 16, k >= 2);

            // words[k], words[k+1], words[k+2] of {q0.x,q0.y,q0.z,q0.w,q1.x,q1.y}
            const float o0 = (k == 0) ? q0.x : (k == 1) ? q0.y : (k == 2) ? q0.z : q0.w;
            const float o1 = (k == 0) ? q0.y : (k == 1) ? q0.z : (k == 2) ? q0.w : q1.x;
            const float o2 = (k == 0) ? q0.z : (k == 1) ? q0.w : (k == 2) ? q1.x : q1.y;

            v[i * 3 + 0] = valid ? o0 : 0.0f;
            v[i * 3 + 1] = valid ? o1 : 0.0f;
            v[i * 3 + 2] = valid ? o2 : 0.0f;
        }

        // out layout: [B, N, C]; 4 pixels * 3 ch = 12 floats = 3 x float4,
        // byte offset = g0*12, multiple of 48 -> 16B aligned. Streaming stores.
        float4* o = reinterpret_cast<float4*>(out + (size_t)g0 * C_);
        __stcs(o + 0, make_float4(v[0], v[1], v[2],  v[3]));
        __stcs(o + 1, make_float4(v[4], v[5], v[6],  v[7]));
        __stcs(o + 2, make_float4(v[8], v[9], v[10], v[11]));
    }
}

extern "C" void kernel_launch(void* const* d_in, const int* in_sizes, int n_in,
                              void* d_out, int out_size)
{
    const float* idx = (const float*)d_in[0];   // [B, 2, N] float32
    const float* src = (const float*)d_in[1];   // [B, Hs, Ws, C] float32
    float* out = (float*)d_out;                 // [B, H_out, W_out, C] float32

    resample_nn_kernel<<<GRID, BLOCK>>>(idx, src, out);
}

// round 11
// speedup vs baseline: 1.1730x; 1.1730x over previous
#include <cuda_runtime.h>

// Fixed problem shapes (from reference setup_inputs)
constexpr int B_    = 16;
constexpr int HS    = 640;
constexpr int WS    = 640;
constexpr int C_    = 3;
constexpr int NPIX  = 512 * 512;          // N = H_out*W_out = 262144 (2^18)
constexpr int NBITS = 18;                 // log2(NPIX)

constexpr int SMS      = 148;
constexpr int CTAS_PSM = 16;
constexpr int GRID     = SMS * CTAS_PSM;              // 2368 -> 16 CTAs on every SM
constexpr int BLOCK    = 128;                         // 64 warps/SM uniform
constexpr int NWARPS   = GRID * BLOCK / 32;           // 9472 warps
constexpr int NGROUPS  = (B_ * NPIX) / 32;            // 131072 groups of 32 pixels

__global__ __launch_bounds__(BLOCK, CTAS_PSM)
void resample_nn_kernel(const float* __restrict__ idx,
                        const float* __restrict__ src,
                        float* __restrict__ out)
{
    const int lane = threadIdx.x & 31;
    const int w0   = (blockIdx.x * BLOCK + threadIdx.x) >> 5;   // global warp id

    // Per-thread constant mapping for the 3 gather/store passes:
    // pass m handles stream word w = lane + 32*m  ->  pixel p = w/3, channel = w%3
    int p_of[3], chb[3];
    #pragma unroll
    for (int m = 0; m < 3; m++) {
        const int w = lane + 32 * m;
        p_of[m] = w / 3;            // source lane holding this pixel's offset
        chb[m]  = (w % 3) * 4;      // channel byte offset
    }

    #pragma unroll 1
    for (int g = w0; g < NGROUPS; g += NWARPS) {
        const int g0 = g * 32;                    // first pixel (global, b*N + n)
        const int b  = g0 >> NBITS;
        const int n0 = g0 & (NPIX - 1);           // multiple of 32, no wrap for +lane

        // idx layout: [B, 2, N] -> rows at b*2N + n, cols at b*2N + N + n
        const float* idx_b = idx + (size_t)b * 2 * NPIX;
        const float r = __ldcs(idx_b + n0 + lane);
        const float c = __ldcs(idx_b + NPIX + n0 + lane);

        // trunc(x + 0.5) -> C int cast truncates toward zero, same semantics
        const int ir = (int)(r + 0.5f);
        const int ic = (int)(c + 0.5f);
        const bool valid = (ir >= 0) & (ic >= 0) & (ir < HS) & (ic < WS);
        const int irc = min(max(ir, 0), HS - 1);
        const int icc = min(max(ic, 0), WS - 1);

        // packed: byte offset of pixel in batch tile (<2^23) | valid flag in bit 31
        const int off    = (irc * WS + icc) * (C_ * 4);
        const int packed = valid ? off : (off | 0x80000000);

        const char* __restrict__ sb =
            reinterpret_cast<const char*>(src) + (size_t)b * HS * WS * C_ * sizeof(float);

        // 3 passes: gather stream word w = lane + 32m; adjacent lanes share the
        // pixel's 128B line -> L1 coalesces to ~11 wavefronts per pass.
        float val[3];
        #pragma unroll
        for (int m = 0; m < 3; m++) {
            const int pk = __shfl_sync(0xffffffffu, packed, p_of[m]);
            const float gv =
                __ldg(reinterpret_cast<const float*>(sb + (pk & 0x7fffffff) + chb[m]));
            val[m] = (pk >= 0) ? gv : 0.0f;
        }

        // out layout: [B, N, C]; group covers words [3*g0, 3*g0+96) — the same
        // linear stream we gathered. Perfectly coalesced streaming stores.
        float* ob = out + (size_t)g0 * C_;
        #pragma unroll
        for (int m = 0; m < 3; m++) {
            __stcs(ob + lane + 32 * m, val[m]);
        }
    }
}

extern "C" void kernel_launch(void* const* d_in, const int* in_sizes, int n_in,
                              void* d_out, int out_size)
{
    const float* idx = (const float*)d_in[0];   // [B, 2, N] float32
    const float* src = (const float*)d_in[1];   // [B, Hs, Ws, C] float32
    float* out = (float*)d_out;                 // [B, H_out, W_out, C] float32

    resample_nn_kernel<<<GRID, BLOCK>>>(idx, src, out);
}